// round 6
// baseline (speedup 1.0000x reference)
#include <cuda_runtime.h>
#include <cuda_fp16.h>

// In (4,8,262144) f32, NNsites (13,262144) i32, Weights (8,8,16) f32,
// bias (8,8) f32. Output (4,8,262144) f32.
#define NSITES_MAX 262144

// Site-major features, fp16, PRE-SCALED by log2(e). Row = 32 half = 64 B.
// g_T[n][bo] = log2e *  sum_i Wn[o][i]*In[b][i][n]
// g_S[n][bo] = log2e * (sum_i Ws[o][i]*In[b][i][n] + beff[o])
__device__ __align__(256) __half2 g_T[NSITES_MAX * 16];
__device__ __align__(256) __half2 g_S[NSITES_MAX * 16];

__device__ __forceinline__ __half2 u32_as_h2(unsigned v) {
    return *reinterpret_cast<const __half2*>(&v);
}

// acc (packed f32x2) += {a, b}
__device__ __forceinline__ void acc_f32x2(unsigned long long& acc, float a, float b) {
    unsigned long long t;
    asm("mov.b64 %0, {%1, %2};" : "=l"(t) : "f"(a), "f"(b));
    asm("add.rn.f32x2 %0, %0, %1;" : "+l"(acc) : "l"(t));
}

// ---------------------------------------------------------------------------
// Pass 1: compute BOTH T' and S' (fp16, log2e-scaled), site-major.
// 128 sites per CTA. smem stride 129 -> conflict-free column reads.
// ---------------------------------------------------------------------------
__global__ __launch_bounds__(256) void pass1_kernel(
    const float* __restrict__ In,      // In[(b*8+i)*N + n]
    const float* __restrict__ W,       // W[j*128 + o*16 + k]
    const float* __restrict__ bias,    // bias[j*8 + o]
    int N)
{
    __shared__ float sWn[8][8];
    __shared__ float sWs[8][8];
    __shared__ float sbe[8];
    __shared__ float sin_[32][129];

    const int tid  = threadIdx.x;
    const int base = blockIdx.x * 128;

    if (tid < 64) {
        int o = tid >> 3, i = tid & 7;
        float wn = 0.f, ws = 0.f;
        #pragma unroll
        for (int j = 0; j < 8; j++) {
            ws += W[j * 128 + o * 16 + i];
            wn += W[j * 128 + o * 16 + 8 + i];
        }
        sWn[o][i] = wn * 1.44269504f;   // fold log2e
        sWs[o][i] = ws * 1.44269504f;
        if (i == 0) {
            float be = 0.f;
            #pragma unroll
            for (int j = 0; j < 8; j++) be += bias[j * 8 + o];
            sbe[o] = be * 1.44269504f;
        }
    }
    #pragma unroll
    for (int k = 0; k < 16; k++) {
        int idx = tid + k * 256;
        int r = idx >> 7, c = idx & 127;
        sin_[r][c] = In[r * N + base + c];
    }
    __syncthreads();

    const int w  = tid >> 5, lane = tid & 31;
    const int j  = lane & 7;                // bo group: 4j..4j+3
    const int b  = j >> 1, o0 = (j & 1) * 4;

    #pragma unroll
    for (int st = 0; st < 4; st++) {
        const int sl = st * 32 + w * 4 + (lane >> 3);

        float x[8];
        #pragma unroll
        for (int i = 0; i < 8; i++) x[i] = sin_[b * 8 + i][sl];

        float tv[4], sv[4];
        #pragma unroll
        for (int q = 0; q < 4; q++) {
            float at = 0.f, as = sbe[o0 + q];
            #pragma unroll
            for (int i = 0; i < 8; i++) {
                at = fmaf(sWn[o0 + q][i], x[i], at);
                as = fmaf(sWs[o0 + q][i], x[i], as);
            }
            tv[q] = at; sv[q] = as;
        }
        __half2 th0 = __floats2half2_rn(tv[0], tv[1]);
        __half2 th1 = __floats2half2_rn(tv[2], tv[3]);
        __half2 sh0 = __floats2half2_rn(sv[0], sv[1]);
        __half2 sh1 = __floats2half2_rn(sv[2], sv[3]);
        uint2 ut = make_uint2(*reinterpret_cast<unsigned*>(&th0),
                              *reinterpret_cast<unsigned*>(&th1));
        uint2 us = make_uint2(*reinterpret_cast<unsigned*>(&sh0),
                              *reinterpret_cast<unsigned*>(&sh1));
        ((uint2*)g_T)[(base + sl) * 8 + j] = ut;
        ((uint2*)g_S)[(base + sl) * 8 + j] = us;
    }
}

// ---------------------------------------------------------------------------
// Pass 2: out[bo][n] = sum_z softplus( S[n][bo] + T[NN[z+1][n]][bo] )
// log2e-scaled:  sum sp(x) = ln2 * sum max(x',0) + log( prod (1+2^{-|x'|}) )
// NO shared memory, NO barriers. Lane = (site, b): 4 lanes/site, 8 sites/warp.
// S: one coalesced LDG.128. Gathers: LDG.128 per (site, z).
// Stores: per bo, 8 lanes cover 8 consecutive n -> 32B sectors.
// ---------------------------------------------------------------------------
__global__ __launch_bounds__(256, 6) void pass2_kernel(
    const int*   __restrict__ NN,      // NN[z*N + n]
    float*       __restrict__ out,     // out[bo*N + n]
    int N)
{
    const int tid  = threadIdx.x;
    const int base = blockIdx.x * 64;
    const int w    = tid >> 5, lane = tid & 31;
    const int sl   = w * 8 + (lane >> 2);   // site within 64-tile
    const int jj   = lane & 3;              // batch b; this thread: bo = jj*8..jj*8+7
    const int n    = base + sl;

    // Own-site S' row: 8 half (log2e-scaled), one coalesced 16B load.
    uint4 s4 = ((const uint4*)g_S)[n * 4 + jj];
    __half2 s2[4] = { u32_as_h2(s4.x), u32_as_h2(s4.y),
                      u32_as_h2(s4.z), u32_as_h2(s4.w) };

    // Neighbor indices: warp-uniform per 4 lanes; 8 sites = 32B/warp per z.
    int idx[12];
    #pragma unroll
    for (int z = 0; z < 12; z++) idx[z] = NN[(z + 1) * N + n];

    const __half2 one2 = __float2half2_rn(1.f);
    const __half2 m22  = __float2half2_rn(-2.f);
    const uint4* __restrict__ Tp = (const uint4*)g_T;

    __half2 prod[4] = {one2, one2, one2, one2};
    unsigned long long lin[4] = {0ull, 0ull, 0ull, 0ull};

    #pragma unroll
    for (int zc = 0; zc < 3; zc++) {
        uint4 t4[4];
        #pragma unroll
        for (int z = 0; z < 4; z++)
            t4[z] = Tp[idx[zc * 4 + z] * 4 + jj];   // 64B row gather
        #pragma unroll
        for (int p = 0; p < 2; p++) {
            const uint4& ta = t4[p * 2];
            const uint4& tb = t4[p * 2 + 1];
            unsigned tau[4] = {ta.x, ta.y, ta.z, ta.w};
            unsigned tbu[4] = {tb.x, tb.y, tb.z, tb.w};
            #pragma unroll
            for (int m = 0; m < 4; m++) {
                __half2 tha = u32_as_h2(tau[m]);
                __half2 thb = u32_as_h2(tbu[m]);
                __half2 ra = __hfma2_relu(s2[m], one2, tha);          // max(x',0)
                __half2 rb = __hfma2_relu(s2[m], one2, thb);
                __half2 ma = __hadd2(__hfma2(ra, m22, tha), s2[m]);   // -|x'|
                __half2 mb = __hadd2(__hfma2(rb, m22, thb), s2[m]);
                __half2 e;
                e = h2exp2(ma); prod[m] = __hfma2(prod[m], e, prod[m]);
                e = h2exp2(mb); prod[m] = __hfma2(prod[m], e, prod[m]);
                __half2 rp = __hadd2(ra, rb);        // pair-sum in f16
                float2 f = __half22float2(rp);
                acc_f32x2(lin[m], f.x, f.y);
            }
        }
    }

    const float ln2 = 0.69314718f;
    #pragma unroll
    for (int m = 0; m < 4; m++) {
        float lx, ly;
        asm("mov.b64 {%0, %1}, %2;" : "=f"(lx), "=f"(ly) : "l"(lin[m]));
        float r0 = fmaf(ln2, lx, __logf(__low2float (prod[m])));
        float r1 = fmaf(ln2, ly, __logf(__high2float(prod[m])));
        out[(jj * 8 + 2 * m + 0) * N + n] = r0;   // 8 lanes -> 8 consecutive n
        out[(jj * 8 + 2 * m + 1) * N + n] = r1;
    }
}

extern "C" void kernel_launch(void* const* d_in, const int* in_sizes, int n_in,
                              void* d_out, int out_size)
{
    const float* In   = (const float*)d_in[0];
    const int*   NN   = (const int*)  d_in[1];
    const float* W    = (const float*)d_in[2];
    const float* bias = (const float*)d_in[3];
    float*       out  = (float*)d_out;

    const int N = in_sizes[0] / 32;

    pass1_kernel<<<N / 128, 256>>>(In, W, bias, N);
    pass2_kernel<<<N / 64, 256>>>(NN, out, N);
}